// round 13
// baseline (speedup 1.0000x reference)
#include <cuda_runtime.h>
#include <cuda_bf16.h>

// Scratch for segment start offsets. R = 250000 (+1 sentinel). __device__
// global => no allocation anywhere in kernel_launch.
#define MAX_R_PLUS_1 (1 << 22)
__device__ int g_seg_start[MAX_R_PLUS_1];

#define RPW 8    // residues per warp (boundaries live in lanes 0..RPW)
#define UNR 4    // float4 load batch depth (64B per thread in flight)
#define IPT 8    // indices per thread in the boundary pass (2x int4)

// Device-side dtype probe: under int64 the word at any odd position is a high
// word == 0; under int32 it is a sorted index near R-1 (nonzero).
__device__ __forceinline__ bool idx_is_i64(const int* i32, int N) {
    int j = (N - 1) | 1;
    if (j >= N) j -= 2;
    return i32[j] == 0;
}

__device__ __forceinline__ long long load_idx(const void* raw, int i, bool is64) {
    if (is64) return ((const long long*)raw)[i];
    return (long long)((const int*)raw)[i];
}

// Pass 1: boundaries of the sorted index, 8 indices per thread (2x int4 fast
// path). Residues in (prev, cur] start at that atom; the thread owning atom
// N-1 closes trailing empties and the sentinel start[R] = N. Each block
// FENCES and TRIGGERS programmatic completion right after its stores, so the
// dependent pool kernel's grid-sync releases without waiting for grid drain.
__global__ void rp_boundaries_kernel(const void* __restrict__ idx_raw,
                                     int N, int R, int* __restrict__ start) {
    int base = (blockIdx.x * blockDim.x + threadIdx.x) * IPT;
    bool is64 = idx_is_i64((const int*)idx_raw, N);

    if (base < N) {
        long long cur[IPT];
        if (!is64 && base + IPT <= N) {
            const int* p = (const int*)idx_raw + base;
            int4 q0 = __ldg((const int4*)p);
            int4 q1 = __ldg((const int4*)(p + 4));
            cur[0] = q0.x; cur[1] = q0.y; cur[2] = q0.z; cur[3] = q0.w;
            cur[4] = q1.x; cur[5] = q1.y; cur[6] = q1.z; cur[7] = q1.w;
        } else {
#pragma unroll
            for (int k = 0; k < IPT; ++k) {
                int i = base + k;
                cur[k] = (i < N) ? load_idx(idx_raw, i, is64) : 0;
            }
        }

        long long prev = (base == 0) ? -1LL : load_idx(idx_raw, base - 1, is64);

#pragma unroll
        for (int k = 0; k < IPT; ++k) {
            int i = base + k;
            if (i >= N) break;
            long long lo = prev + 1; if (lo < 0) lo = 0;
            long long hi = cur[k];   if (hi > (long long)R) hi = (long long)R;
            for (long long r = lo; r <= hi; ++r) start[r] = i;
            if (i == N - 1) {
                long long lo2 = cur[k] + 1; if (lo2 < 0) lo2 = 0;
                for (long long r = lo2; r <= (long long)R; ++r) start[r] = N;
            }
            prev = cur[k];
        }
    }

    // Release the dependent launch as early as possible: publish this
    // block's start[] writes, then trigger.
    __threadfence();
    cudaTriggerProgrammaticLaunchCompletion();
}

// Pass 2: one WARP per RPW consecutive residues. Lane = float4 column group
// (D/4 = 32 lanes per row). Launched with PDL: blocks come up while pass 1
// still runs, do their index math, then grid-dependency-sync before touching
// start[]. Mainloop identical to the proven R9/R11 version.
__global__ void __launch_bounds__(256, 6)
rp_pool_kernel(const float4* __restrict__ feat4,
               const int* __restrict__ start,
               float4* __restrict__ out4, int R) {
    const unsigned FULL = 0xffffffffu;
    int gwarp = (blockIdx.x * blockDim.x + threadIdx.x) >> 5;
    int lane  = threadIdx.x & 31;

    int r0 = gwarp * RPW;
    int nres = R - r0; if (nres > RPW) nres = RPW;

    // Wait for all boundary blocks' triggers (start[] published).
    cudaGridDependencySynchronize();

    if (r0 >= R) return;

    // Lane l holds boundary start[r0 + min(l, nres)]; boundary(i) = shfl(b, i).
    int b = __ldg(&start[r0 + (lane < nres ? lane : nres)]);

    const int A0 = __shfl_sync(FULL, b, 0);
    const int A1 = __shfl_sync(FULL, b, nres);

    int    rloc   = 0;
    int    sstart = A0;
    int    e      = __shfl_sync(FULL, b, (nres >= 1) ? 1 : 0);
    float4 sum    = make_float4(0.f, 0.f, 0.f, 0.f);

    for (int a = A0; a < A1; a += UNR) {
        float4 v[UNR];
#pragma unroll
        for (int k = 0; k < UNR; ++k) {
            int ai = a + k;
            v[k] = (ai < A1) ? __ldg(&feat4[(size_t)ai * 32 + lane])
                             : make_float4(0.f, 0.f, 0.f, 0.f);
        }
#pragma unroll
        for (int k = 0; k < UNR; ++k) {
            int ai = a + k;
            if (ai >= A1) break;
            while (ai >= e) {               // close segment(s), incl. empties
                int   cnt = e - sstart;
                float inv = 1.0f / (float)(cnt > 0 ? cnt : 1);
                out4[(size_t)(r0 + rloc) * 32 + lane] =
                    make_float4(sum.x * inv, sum.y * inv,
                                sum.z * inv, sum.w * inv);
                sum = make_float4(0.f, 0.f, 0.f, 0.f);
                sstart = e;
                ++rloc;                     // rloc < nres guaranteed (ai < A1)
                e = __shfl_sync(FULL, b, rloc + 1);
            }
            sum.x += v[k].x; sum.y += v[k].y;
            sum.z += v[k].z; sum.w += v[k].w;
        }
    }

    // Flush the last open segment and trailing empty residues.
    while (rloc < nres) {
        int   cnt = e - sstart;
        float inv = 1.0f / (float)(cnt > 0 ? cnt : 1);
        out4[(size_t)(r0 + rloc) * 32 + lane] =
            make_float4(sum.x * inv, sum.y * inv, sum.z * inv, sum.w * inv);
        sum = make_float4(0.f, 0.f, 0.f, 0.f);
        sstart = e;
        ++rloc;
        if (rloc < nres) e = __shfl_sync(FULL, b, rloc + 1);
    }
}

extern "C" void kernel_launch(void* const* d_in, const int* in_sizes, int n_in,
                              void* d_out, int out_size) {
    int fi = (in_sizes[0] >= in_sizes[1]) ? 0 : 1;
    int ii = 1 - fi;
    const float* feat    = (const float*)d_in[fi];
    const void*  idx_raw = d_in[ii];

    int N = in_sizes[ii];            // 2,000,000 atoms
    int D = in_sizes[fi] / N;        // 128
    int R = out_size / D;            // 250,000 residues
    float* out = (float*)d_out;

    int* start = nullptr;
    cudaGetSymbolAddress((void**)&start, g_seg_start);

    int threads  = 256;
    int b_blocks = (N + threads * IPT - 1) / (threads * IPT);
    rp_boundaries_kernel<<<b_blocks, threads>>>(idx_raw, N, R, start);

    // Pool kernel with programmatic dependent launch: its blocks launch while
    // pass 1 runs; the in-kernel cudaGridDependencySynchronize() releases as
    // soon as all pass-1 blocks have fenced + triggered.
    int nwarps      = (R + RPW - 1) / RPW;
    int pool_blocks = (nwarps * 32 + threads - 1) / threads;

    cudaLaunchConfig_t cfg = {};
    cfg.gridDim  = dim3((unsigned)pool_blocks, 1, 1);
    cfg.blockDim = dim3((unsigned)threads, 1, 1);
    cfg.dynamicSmemBytes = 0;
    cfg.stream = 0;
    cudaLaunchAttribute attr[1];
    attr[0].id = cudaLaunchAttributeProgrammaticStreamSerialization;
    attr[0].val.programmaticStreamSerializationAllowed = 1;
    cfg.attrs = attr;
    cfg.numAttrs = 1;

    cudaLaunchKernelEx(&cfg, rp_pool_kernel,
                       (const float4*)feat, (const int*)start,
                       (float4*)out, R);
}

// round 14
// speedup vs baseline: 1.0178x; 1.0178x over previous
#include <cuda_runtime.h>
#include <cuda_bf16.h>

// Scratch for segment start offsets. R = 250000 (+1 sentinel). __device__
// global => no allocation anywhere in kernel_launch.
#define MAX_R_PLUS_1 (1 << 22)
__device__ int g_seg_start[MAX_R_PLUS_1];

#define RPW 8    // residues per warp (boundaries live in lanes 0..RPW)
#define UNR 4    // float4 load batch depth (64B per thread in flight)
#define IPT 4    // indices per thread in the boundary pass

// Device-side dtype probe: under int64 the word at any odd position is a high
// word == 0; under int32 it is a sorted index near R-1 (nonzero).
__device__ __forceinline__ bool idx_is_i64(const int* i32, int N) {
    int j = (N - 1) | 1;
    if (j >= N) j -= 2;
    return i32[j] == 0;
}

__device__ __forceinline__ long long load_idx(const void* raw, int i, bool is64) {
    if (is64) return ((const long long*)raw)[i];
    return (long long)((const int*)raw)[i];
}

// Pass 1: boundaries of the sorted index, 4 indices per thread. Fast path:
// one int4 load (int32 indices, full group). Residues in (prev, cur] start
// at that atom; the thread owning atom N-1 closes trailing empties and the
// sentinel start[R] = N. All writes clamped to [0, R]. NO early PDL trigger:
// the implicit end-of-grid completion keeps waiter blocks off the SMs until
// pass 1 has drained (early trigger measured +2.6us SLOWER in R13).
__global__ void rp_boundaries_kernel(const void* __restrict__ idx_raw,
                                     int N, int R, int* __restrict__ start) {
    int base = (blockIdx.x * blockDim.x + threadIdx.x) * IPT;
    if (base >= N) return;
    bool is64 = idx_is_i64((const int*)idx_raw, N);

    long long cur[IPT];
    if (!is64 && base + IPT <= N) {
        int4 q = __ldg((const int4*)((const int*)idx_raw + base));
        cur[0] = q.x; cur[1] = q.y; cur[2] = q.z; cur[3] = q.w;
    } else {
#pragma unroll
        for (int k = 0; k < IPT; ++k) {
            int i = base + k;
            cur[k] = (i < N) ? load_idx(idx_raw, i, is64) : 0;
        }
    }

    long long prev = (base == 0) ? -1LL : load_idx(idx_raw, base - 1, is64);

#pragma unroll
    for (int k = 0; k < IPT; ++k) {
        int i = base + k;
        if (i >= N) break;
        long long lo = prev + 1; if (lo < 0) lo = 0;
        long long hi = cur[k];   if (hi > (long long)R) hi = (long long)R;
        for (long long r = lo; r <= hi; ++r) start[r] = i;
        if (i == N - 1) {
            long long lo2 = cur[k] + 1; if (lo2 < 0) lo2 = 0;
            for (long long r = lo2; r <= (long long)R; ++r) start[r] = N;
        }
        prev = cur[k];
    }
}

// Pass 2: one WARP per RPW consecutive residues. Lane = float4 column group
// (D/4 = 32 lanes per row). Each warp streams its contiguous atom range with
// UNR-deep wide loads; boundaries live in lane registers via shuffle.
// Default cache policy (streaming hints measured 15us slower). Launched with
// PDL; the grid-dependency-sync precedes any start[] access.
__global__ void __launch_bounds__(256, 6)
rp_pool_kernel(const float4* __restrict__ feat4,
               const int* __restrict__ start,
               float4* __restrict__ out4, int R) {
    const unsigned FULL = 0xffffffffu;
    int gwarp = (blockIdx.x * blockDim.x + threadIdx.x) >> 5;
    int lane  = threadIdx.x & 31;

    int r0 = gwarp * RPW;
    int nres = R - r0; if (nres > RPW) nres = RPW;

    // Wait for the boundary grid to complete (PDL dependency).
    cudaGridDependencySynchronize();

    if (r0 >= R) return;

    // Lane l holds boundary start[r0 + min(l, nres)]; boundary(i) = shfl(b, i).
    int b = __ldg(&start[r0 + (lane < nres ? lane : nres)]);

    const int A0 = __shfl_sync(FULL, b, 0);
    const int A1 = __shfl_sync(FULL, b, nres);

    int    rloc   = 0;
    int    sstart = A0;
    int    e      = __shfl_sync(FULL, b, (nres >= 1) ? 1 : 0);
    float4 sum    = make_float4(0.f, 0.f, 0.f, 0.f);

    for (int a = A0; a < A1; a += UNR) {
        float4 v[UNR];
#pragma unroll
        for (int k = 0; k < UNR; ++k) {
            int ai = a + k;
            v[k] = (ai < A1) ? __ldg(&feat4[(size_t)ai * 32 + lane])
                             : make_float4(0.f, 0.f, 0.f, 0.f);
        }
#pragma unroll
        for (int k = 0; k < UNR; ++k) {
            int ai = a + k;
            if (ai >= A1) break;
            while (ai >= e) {               // close segment(s), incl. empties
                int   cnt = e - sstart;
                float inv = 1.0f / (float)(cnt > 0 ? cnt : 1);
                out4[(size_t)(r0 + rloc) * 32 + lane] =
                    make_float4(sum.x * inv, sum.y * inv,
                                sum.z * inv, sum.w * inv);
                sum = make_float4(0.f, 0.f, 0.f, 0.f);
                sstart = e;
                ++rloc;                     // rloc < nres guaranteed (ai < A1)
                e = __shfl_sync(FULL, b, rloc + 1);
            }
            sum.x += v[k].x; sum.y += v[k].y;
            sum.z += v[k].z; sum.w += v[k].w;
        }
    }

    // Flush the last open segment and trailing empty residues.
    while (rloc < nres) {
        int   cnt = e - sstart;
        float inv = 1.0f / (float)(cnt > 0 ? cnt : 1);
        out4[(size_t)(r0 + rloc) * 32 + lane] =
            make_float4(sum.x * inv, sum.y * inv, sum.z * inv, sum.w * inv);
        sum = make_float4(0.f, 0.f, 0.f, 0.f);
        sstart = e;
        ++rloc;
        if (rloc < nres) e = __shfl_sync(FULL, b, rloc + 1);
    }
}

extern "C" void kernel_launch(void* const* d_in, const int* in_sizes, int n_in,
                              void* d_out, int out_size) {
    int fi = (in_sizes[0] >= in_sizes[1]) ? 0 : 1;
    int ii = 1 - fi;
    const float* feat    = (const float*)d_in[fi];
    const void*  idx_raw = d_in[ii];

    int N = in_sizes[ii];            // 2,000,000 atoms
    int D = in_sizes[fi] / N;        // 128
    int R = out_size / D;            // 250,000 residues
    float* out = (float*)d_out;

    int* start = nullptr;
    cudaGetSymbolAddress((void**)&start, g_seg_start);

    int threads  = 256;
    int b_blocks = (N + threads * IPT - 1) / (threads * IPT);
    rp_boundaries_kernel<<<b_blocks, threads>>>(idx_raw, N, R, start);

    // Pool kernel with programmatic dependent launch (implicit completion):
    // overlaps launch/setup with the boundary pass; correctness preserved by
    // the in-kernel cudaGridDependencySynchronize().
    int nwarps      = (R + RPW - 1) / RPW;
    int pool_blocks = (nwarps * 32 + threads - 1) / threads;

    cudaLaunchConfig_t cfg = {};
    cfg.gridDim  = dim3((unsigned)pool_blocks, 1, 1);
    cfg.blockDim = dim3((unsigned)threads, 1, 1);
    cfg.dynamicSmemBytes = 0;
    cfg.stream = 0;
    cudaLaunchAttribute attr[1];
    attr[0].id = cudaLaunchAttributeProgrammaticStreamSerialization;
    attr[0].val.programmaticStreamSerializationAllowed = 1;
    cfg.attrs = attr;
    cfg.numAttrs = 1;

    cudaLaunchKernelEx(&cfg, rp_pool_kernel,
                       (const float4*)feat, (const int*)start,
                       (float4*)out, R);
}